// round 13
// baseline (speedup 1.0000x reference)
#include <cuda_runtime.h>
#include <math.h>
#include <stdint.h>

#define B_   256
#define T_   256
#define INSZ 512
#define HD   1024
#define NBLK 128
#define NTHR 256
#define NCH  24

typedef unsigned long long u64;

// k-major (transposed) operand buffers, built once per launch in init pass
__device__ float g_xT[T_ * INSZ * B_];          // [t][k][b]
__device__ float g_hT[2][4 * HD * B_];          // [pp][s*HD+j][b]
__device__ float g_pT[2][INSZ * B_];            // [pp][o][b]
__device__ float g_WxT[4 * INSZ * 3 * HD];      // [wi][k][J]
__device__ float g_WhT[4 * HD * 3 * HD];
__device__ float g_WoT[4 * (HD + INSZ) * INSZ]; // [wi][k][o]

// global (init-only) sense barrier
__device__ unsigned g_count;
__device__ volatile unsigned g_sense;
// per-group monotonic barrier counters (stride 16 u64 = 128 B padding)
__device__ u64 g_bar[4 * 16];

__device__ __forceinline__ void grid_barrier(unsigned& ls)
{
    __syncthreads();
    if (threadIdx.x == 0) {
        unsigned s = ls ^ 1u;
        __threadfence();
        if (atomicAdd(&g_count, 1u) == NBLK - 1) {
            g_count = 0;
            __threadfence();
            g_sense = s;
        } else {
            while (g_sense != s) { __nanosleep(32); }
        }
        __threadfence();
        ls = s;
    }
    __syncthreads();
}

__device__ __forceinline__ u64 pack2(float lo, float hi)
{ u64 r; asm("mov.b64 %0, {%1, %2};" : "=l"(r) : "f"(lo), "f"(hi)); return r; }
__device__ __forceinline__ void unpack2(u64 v, float& lo, float& hi)
{ asm("mov.b64 {%0, %1}, %2;" : "=f"(lo), "=f"(hi) : "l"(v)); }
__device__ __forceinline__ void ffma2(u64& d, u64 a, u64 b)
{ asm("fma.rn.f32x2 %0, %1, %2, %0;" : "+l"(d) : "l"(a), "l"(b)); }

__device__ __forceinline__ uint32_t smem_u32(const void* p)
{ uint32_t a; asm("{ .reg .u64 t; cvta.to.shared.u64 t, %1; cvt.u32.u64 %0, t; }" : "=r"(a) : "l"(p)); return a; }

__device__ __forceinline__ void cp16(uint32_t dst, const float* src)
{ asm volatile("cp.async.cg.shared.global [%0], [%1], 16;" :: "r"(dst), "l"(src)); }

#define CPCOMMIT() asm volatile("cp.async.commit_group;" ::: "memory")
#define CPWAIT1()  asm volatile("cp.async.wait_group 1;" ::: "memory")
#define CPWAIT0()  asm volatile("cp.async.wait_group 0;" ::: "memory")

#define STG_B 40960
#define SMEMB (3 * STG_B)

// ---------------- cp.async issue helpers ----------------
__device__ __forceinline__ void issue_gate(uint32_t stg, const float* Ap, const float* Wp, int tid)
{
#pragma unroll
    for (int i = 0; i < 4; i++) {
        int idx = tid + i * 256, row = idx >> 4, seg = idx & 15;
        cp16(stg + row * 256 + seg * 16, Ap + (size_t)row * B_ + seg * 4);
    }
#pragma unroll
    for (int i = 0; i < 6; i++) {
        int idx = tid + i * 256, tile = idx >> 9, rem = idx & 511, row = rem >> 3, seg = rem & 7;
        cp16(stg + 16384 + tile * 8192 + row * 128 + seg * 16,
             Wp + (size_t)row * (3 * HD) + tile * HD + seg * 4);
    }
}

__device__ __forceinline__ void issue_pred(uint32_t stg, const float* Ap, const float* Wp, int tid)
{
#pragma unroll
    for (int i = 0; i < 4; i++) {
        int idx = tid + i * 256, row = idx >> 4, seg = idx & 15;
        cp16(stg + row * 256 + seg * 16, Ap + (size_t)row * B_ + seg * 4);
    }
    { int row = tid >> 2, seg = tid & 3;
      cp16(stg + 16384 + row * 64 + seg * 16, Wp + (size_t)row * INSZ + seg * 4); }
}

// chunk maps: gate = 16 h-chunks then 8 x-chunks; pred = 8 x then 16 h
__device__ __forceinline__ const float* gAp(const float* xb_, const float* hb, int c, int b0)
{ return (c < 16) ? hb + (size_t)(c * 64) * B_ + b0 : xb_ + (size_t)((c - 16) * 64) * B_ + b0; }
__device__ __forceinline__ const float* gWp(const float* wx, const float* wh, int c, int j0)
{ return (c < 16) ? wh + (size_t)(c * 64) * (3 * HD) + j0 : wx + (size_t)((c - 16) * 64) * (3 * HD) + j0; }
__device__ __forceinline__ const float* pAp(const float* xb_, const float* hb, int c, int b0)
{ return (c < 8) ? xb_ + (size_t)(c * 64) * B_ + b0 : hb + (size_t)((c - 8) * 64) * B_ + b0; }

// ---------------- compute ----------------
__device__ __forceinline__ void gate_compute(const char* stg, int tx, int ty,
    u64 (&au)[2][2], u64 (&ar)[2][2], u64 (&an)[2][2])
{
    const float* As = (const float*)stg;
    const char* W = stg + 16384;
#pragma unroll 8
    for (int kk = 0; kk < 64; kk++) {
        float2 a2 = *(const float2*)(As + kk * 64 + ty * 2);
        u64 A0 = pack2(a2.x, a2.x), A1 = pack2(a2.y, a2.y);
        ulonglong2 wu = *(const ulonglong2*)(W + kk * 128 + tx * 16);
        ulonglong2 wr = *(const ulonglong2*)(W + 8192 + kk * 128 + tx * 16);
        ulonglong2 wn = *(const ulonglong2*)(W + 16384 + kk * 128 + tx * 16);
        ffma2(au[0][0], A0, wu.x); ffma2(au[1][0], A0, wu.y);
        ffma2(au[0][1], A1, wu.x); ffma2(au[1][1], A1, wu.y);
        ffma2(ar[0][0], A0, wr.x); ffma2(ar[1][0], A0, wr.y);
        ffma2(ar[0][1], A1, wr.x); ffma2(ar[1][1], A1, wr.y);
        ffma2(an[0][0], A0, wn.x); ffma2(an[1][0], A0, wn.y);
        ffma2(an[0][1], A1, wn.x); ffma2(an[1][1], A1, wn.y);
    }
}

__device__ __forceinline__ void pred_compute(const char* stg, int tx, int ty, u64 (&acc)[2])
{
    const float* As = (const float*)stg;
    const char* W = stg + 16384;
#pragma unroll 8
    for (int kk = 0; kk < 64; kk++) {
        float2 a2 = *(const float2*)(As + kk * 64 + ty * 2);
        u64 wv = *(const u64*)(W + kk * 64 + tx * 8);
        ffma2(acc[0], pack2(a2.x, a2.x), wv);
        ffma2(acc[1], pack2(a2.y, a2.y), wv);
    }
}

// ---------------------------------------------------------------------------
__global__ void __launch_bounds__(NTHR) sgru_kernel(
    const float* __restrict__ xb, const float* __restrict__ h0,
    const float* __restrict__ Wx, const float* __restrict__ bx,
    const float* __restrict__ Wh, const float* __restrict__ bh,
    const float* __restrict__ Wo, const float* __restrict__ bo,
    float* __restrict__ out)
{
    extern __shared__ __align__(16) char smx[];
    const uint32_t smb = smem_u32(smx);
    const int tid = threadIdx.x, bid = blockIdx.x;
    const int tx = tid & 7, ty = tid >> 3;
    const int grp = bid >> 5, cid = bid & 31;
    const int j0 = cid * 32, o0 = cid * 16, b0 = grp * 64;
    unsigned ls = g_sense;
    const u64 bbase = g_bar[grp * 16];   // residue from previous replay; uniform pre-barrier
    u64 ep = 0;                          // arrives issued by this CTA

    // ================= init pass: build k-major copies =================
    {
        const long GT = NBLK * NTHR;
        const long g0 = (long)bid * NTHR + tid;
        for (long d = g0; d < (long)T_ * INSZ * B_; d += GT) {
            int b = (int)(d & 255); long rest = d >> 8;
            int k = (int)(rest & 511); int tt = (int)(rest >> 9);
            g_xT[d] = __ldg(xb + ((size_t)b * T_ + tt) * INSZ + k);
        }
        for (long d = g0; d < (long)4 * INSZ * 3 * HD; d += GT) {
            int J = (int)(d % 3072); long rest = d / 3072;
            int k = (int)(rest & 511); int wi = (int)(rest >> 9);
            g_WxT[d] = __ldg(Wx + ((size_t)wi * 3072 + J) * INSZ + k);
        }
        for (long d = g0; d < (long)4 * HD * 3 * HD; d += GT) {
            int J = (int)(d % 3072); long rest = d / 3072;
            int k = (int)(rest & 1023); int wi = (int)(rest >> 10);
            g_WhT[d] = __ldg(Wh + ((size_t)wi * 3072 + J) * HD + k);
        }
        for (long d = g0; d < (long)4 * (HD + INSZ) * INSZ; d += GT) {
            int o = (int)(d & 511); long rest = d >> 9;
            int k = (int)(rest % 1536); int wi = (int)(rest / 1536);
            g_WoT[d] = __ldg(Wo + ((size_t)wi * INSZ + o) * (HD + INSZ) + k);
        }
        for (long d = g0; d < (long)4 * HD * B_; d += GT) {
            int b = (int)(d & 255); long rest = d >> 8;
            int j = (int)(rest & 1023); int s = (int)(rest >> 10);
            g_hT[0][d] = __ldg(h0 + ((size_t)b * 4 + s) * HD + j);
        }
    }
    grid_barrier(ls);

    // prologue for stack 0 (gate h-chunks 0,1)
    {
        const float* h00 = g_hT[0];
        const float* wh0 = g_WhT;
        issue_gate(smb, gAp(nullptr, h00, 0, b0), gWp(nullptr, wh0, 0, j0), tid); CPCOMMIT();
        issue_gate(smb + STG_B, gAp(nullptr, h00, 1, b0), gWp(nullptr, wh0, 1, j0), tid); CPCOMMIT();
    }

#pragma unroll 1
    for (int sk = 0; sk < T_ * 4; sk++) {
        const int t = sk >> 2, s = sk & 3;
        const int rd = t & 1, wr = rd ^ 1;
        const int wi = (s == 3) ? 2 : s;
        const float* xbase = (s == 0) ? g_xT + (size_t)t * INSZ * B_ : g_pT[(s - 1) & 1];
        const float* hrdT = g_hT[rd] + (size_t)s * HD * B_;
        float*       hwrT = g_hT[wr] + (size_t)s * HD * B_;
        const float* wxT = g_WxT + (size_t)wi * INSZ * 3 * HD;
        const float* whT = g_WhT + (size_t)wi * HD * 3 * HD;
        const float* woT = g_WoT + (size_t)wi * (HD + INSZ) * INSZ;
        const float* bx3 = bx + wi * 3 * HD;
        const float* bh3 = bh + wi * 3 * HD;

        // ================= GATE (16 h-chunks, then 8 x-chunks) =================
        u64 au[2][2], ar[2][2], axn[2][2], ahn[2][2];
#pragma unroll
        for (int p = 0; p < 2; p++) {
            int jg = j0 + tx * 4 + p * 2;
            u64 bu = pack2(bx3[jg] + bh3[jg], bx3[jg + 1] + bh3[jg + 1]);
            u64 br = pack2(bx3[HD + jg] + bh3[HD + jg], bx3[HD + jg + 1] + bh3[HD + jg + 1]);
            u64 bxn = pack2(bx3[2 * HD + jg], bx3[2 * HD + jg + 1]);
            u64 bhn = pack2(bh3[2 * HD + jg], bh3[2 * HD + jg + 1]);
            au[p][0] = au[p][1] = bu; ar[p][0] = ar[p][1] = br;
            axn[p][0] = axn[p][1] = bxn; ahn[p][0] = ahn[p][1] = bhn;
        }
#pragma unroll 1
        for (int c = 0; c < NCH; c++) {
            if (c < NCH - 1) CPWAIT1(); else CPWAIT0();
            if (c == 14 && tid == 0) {   // guard pred(s-1) outputs before first x issue
                while (*(volatile u64*)&g_bar[grp * 16] - bbase < ep * 32ull) __nanosleep(64);
                __threadfence();
            }
            __syncthreads();
            if (c + 2 < NCH) {
                issue_gate(smb + ((c + 2) % 3) * STG_B,
                           gAp(xbase, hrdT, c + 2, b0), gWp(wxT, whT, c + 2, j0), tid);
                CPCOMMIT();
            }
            if (c < 16) gate_compute(smx + (c % 3) * STG_B, tx, ty, au, ar, ahn);
            else        gate_compute(smx + (c % 3) * STG_B, tx, ty, au, ar, axn);
        }
        // pred prologue (x-chunks; deps already guarded) — hide behind epilogue
        issue_pred(smb, pAp(xbase, hwrT, 0, b0), woT + o0, tid); CPCOMMIT();
        issue_pred(smb + STG_B, pAp(xbase, hwrT, 1, b0), woT + (size_t)64 * INSZ + o0, tid); CPCOMMIT();
        // gate epilogue: 4j x 2b per thread
#pragma unroll
        for (int i = 0; i < 2; i++) {
            int b = b0 + ty * 2 + i;
            int jg = j0 + tx * 4;
            float uv[4], rv[4], xnv[4], hnv[4];
#pragma unroll
            for (int p = 0; p < 2; p++) {
                unpack2(au[p][i], uv[p * 2], uv[p * 2 + 1]);
                unpack2(ar[p][i], rv[p * 2], rv[p * 2 + 1]);
                unpack2(axn[p][i], xnv[p * 2], xnv[p * 2 + 1]);
                unpack2(ahn[p][i], hnv[p * 2], hnv[p * 2 + 1]);
            }
#pragma unroll
            for (int jj = 0; jj < 4; jj++) {
                float u = 1.0f / (1.0f + expf(-uv[jj]));
                float r = 1.0f / (1.0f + expf(-rv[jj]));
                float n = tanhf(xnv[jj] + r * hnv[jj]);
                float ho = __ldcg(hrdT + (size_t)(jg + jj) * B_ + b);
                hwrT[(size_t)(jg + jj) * B_ + b] = u * ho + (1.0f - u) * n;
            }
        }
        __syncthreads();
        if (tid == 0) { __threadfence(); atomicAdd(&g_bar[grp * 16], 1ull); }
        ep++;   // BarH arrived

        // ================= PRED (8 x-chunks, then 16 h-chunks) =================
        {
            const float* bop = bo + wi * INSZ;
            u64 acc[2];
            acc[0] = acc[1] = pack2(bop[o0 + tx * 2], bop[o0 + tx * 2 + 1]);
#pragma unroll 1
            for (int c = 0; c < NCH; c++) {
                if (c < NCH - 1) CPWAIT1(); else CPWAIT0();
                if (c == 6 && tid == 0) {   // guard h_new of whole group before first h issue
                    while (*(volatile u64*)&g_bar[grp * 16] - bbase < ep * 32ull) __nanosleep(64);
                    __threadfence();
                }
                __syncthreads();
                if (c + 2 < NCH) {
                    issue_pred(smb + ((c + 2) % 3) * STG_B,
                               pAp(xbase, hwrT, c + 2, b0),
                               woT + (size_t)((c + 2) * 64) * INSZ + o0, tid);
                    CPCOMMIT();
                }
                pred_compute(smx + (c % 3) * STG_B, tx, ty, acc);
            }
            // next-stack gate prologue (h-chunks, no dependency) — hide behind epilogue
            if (sk + 1 < T_ * 4) {
                int tn = (sk + 1) >> 2, sn = (sk + 1) & 3;
                int win = (sn == 3) ? 2 : sn;
                const float* hrdn = g_hT[tn & 1] + (size_t)sn * HD * B_;
                const float* whn = g_WhT + (size_t)win * HD * 3 * HD;
                issue_gate(smb, gAp(nullptr, hrdn, 0, b0), gWp(nullptr, whn, 0, j0), tid); CPCOMMIT();
                issue_gate(smb + STG_B, gAp(nullptr, hrdn, 1, b0), gWp(nullptr, whn, 1, j0), tid); CPCOMMIT();
            }
            // pred epilogue
            int o = o0 + tx * 2;
#pragma unroll
            for (int i = 0; i < 2; i++) {
                int b = b0 + ty * 2 + i;
                float v0, v1;
                unpack2(acc[i], v0, v1);
                if (s == 3) {
                    *(float2*)(out + ((size_t)b * T_ + t) * INSZ + o) = make_float2(v0, v1);
                } else {
                    float* pT = g_pT[s & 1];
                    pT[(size_t)o * B_ + b] = v0;
                    pT[(size_t)(o + 1) * B_ + b] = v1;
                }
            }
        }
        __syncthreads();
        if (tid == 0) { __threadfence(); atomicAdd(&g_bar[grp * 16], 1ull); }
        ep++;   // BarX arrived
    }

    // ---- final group barrier: all 32 CTAs of this group fully done ----
    if (tid == 0) {
        while (*(volatile u64*)&g_bar[grp * 16] - bbase < ep * 32ull) __nanosleep(64);
        __threadfence();
    }
    __syncthreads();

    // ---- final h copy-out (group-scoped: b in [b0, b0+64)) ----
    {
        const int GT = 32 * NTHR;
        for (int d = cid * NTHR + tid; d < 64 * 4 * HD; d += GT) {
            int lb = d >> 12, rest = d & 4095;
            int s2 = rest >> 10, j = rest & 1023;
            int b = b0 + lb;
            out[(size_t)B_ * T_ * INSZ + ((size_t)b * 4 + s2) * HD + j] =
                __ldcg(&g_hT[0][((size_t)s2 * HD + j) * B_ + b]);
        }
    }
    // ---- log_softmax (group-scoped rows) ----
    {
        int w = tid >> 5, ln = tid & 31;
        for (int rr = cid * 8 + w; rr < 64 * T_; rr += 32 * 8) {
            int lb = rr >> 8, t2 = rr & 255;
            float* p = out + ((size_t)(b0 + lb) * T_ + t2) * INSZ;
            float v[16], m = -1e30f;
#pragma unroll
            for (int i = 0; i < 16; i++) { v[i] = __ldcg(p + ln + i * 32); m = fmaxf(m, v[i]); }
#pragma unroll
            for (int o = 16; o > 0; o >>= 1) m = fmaxf(m, __shfl_xor_sync(~0u, m, o));
            float sv = 0.0f;
#pragma unroll
            for (int i = 0; i < 16; i++) sv += expf(v[i] - m);
#pragma unroll
            for (int o = 16; o > 0; o >>= 1) sv += __shfl_xor_sync(~0u, sv, o);
            float lv = m + logf(sv);
#pragma unroll
            for (int i = 0; i < 16; i++) p[ln + i * 32] = v[i] - lv;
        }
    }
}

// ---------------------------------------------------------------------------
extern "C" void kernel_launch(void* const* d_in, const int* in_sizes, int n_in,
                              void* d_out, int out_size)
{
    cudaFuncSetAttribute(sgru_kernel, cudaFuncAttributeMaxDynamicSharedMemorySize, SMEMB);
    sgru_kernel<<<NBLK, NTHR, SMEMB>>>(
        (const float*)d_in[0], (const float*)d_in[1], (const float*)d_in[2],
        (const float*)d_in[3], (const float*)d_in[4], (const float*)d_in[5],
        (const float*)d_in[6], (const float*)d_in[7], (float*)d_out);
}

// round 14
// speedup vs baseline: 1.2213x; 1.2213x over previous
#include <cuda_runtime.h>
#include <math.h>
#include <stdint.h>

#define B_   256
#define T_   256
#define INSZ 512
#define HD   1024
#define NBLK 128
#define NTHR 256
#define NCH  24

typedef unsigned long long u64;

// k-major (transposed) operand buffers, built once per launch in init pass
__device__ float g_xT[T_ * INSZ * B_];          // [t][k][b]
__device__ float g_hT[2][4 * HD * B_];          // [pp][s*HD+j][b]
__device__ float g_pT[2][INSZ * B_];            // [pp][o][b]
__device__ float g_WxT[4 * INSZ * 3 * HD];      // [wi][k][J]
__device__ float g_WhT[4 * HD * 3 * HD];
__device__ float g_WoT[4 * (HD + INSZ) * INSZ]; // [wi][k][o]

__device__ unsigned g_count;
__device__ volatile unsigned g_sense;

__device__ __forceinline__ void grid_barrier(unsigned& ls)
{
    __syncthreads();
    if (threadIdx.x == 0) {
        unsigned s = ls ^ 1u;
        __threadfence();
        if (atomicAdd(&g_count, 1u) == NBLK - 1) {
            g_count = 0;
            __threadfence();
            g_sense = s;
        } else {
            while (g_sense != s) { __nanosleep(32); }
        }
        __threadfence();
        ls = s;
    }
    __syncthreads();
}

__device__ __forceinline__ u64 pack2(float lo, float hi)
{ u64 r; asm("mov.b64 %0, {%1, %2};" : "=l"(r) : "f"(lo), "f"(hi)); return r; }
__device__ __forceinline__ void unpack2(u64 v, float& lo, float& hi)
{ asm("mov.b64 {%0, %1}, %2;" : "=f"(lo), "=f"(hi) : "l"(v)); }
__device__ __forceinline__ void ffma2(u64& d, u64 a, u64 b)
{ asm("fma.rn.f32x2 %0, %1, %2, %0;" : "+l"(d) : "l"(a), "l"(b)); }

__device__ __forceinline__ uint32_t smem_u32(const void* p)
{ uint32_t a; asm("{ .reg .u64 t; cvta.to.shared.u64 t, %1; cvt.u32.u64 %0, t; }" : "=r"(a) : "l"(p)); return a; }

__device__ __forceinline__ void cp16(uint32_t dst, const float* src)
{ asm volatile("cp.async.cg.shared.global [%0], [%1], 16;" :: "r"(dst), "l"(src)); }

#define CPCOMMIT() asm volatile("cp.async.commit_group;" ::: "memory")
#define CPWAIT1()  asm volatile("cp.async.wait_group 1;" ::: "memory")
#define CPWAIT0()  asm volatile("cp.async.wait_group 0;" ::: "memory")

// stage layout: A tile [64k][64b] floats @0 (16384 B); W tiles @16384
// gate: 3 x [64k][32j] (8192 B each); pred: [64k][16o] (4096 B)
#define STG_B 40960
#define SMEMB (3 * STG_B)

// ---------------- cp.async issue helpers ----------------
__device__ __forceinline__ void issue_gate(uint32_t stg, const float* Ap, const float* Wp, int tid)
{
#pragma unroll
    for (int i = 0; i < 4; i++) {
        int idx = tid + i * 256, row = idx >> 4, seg = idx & 15;
        cp16(stg + row * 256 + seg * 16, Ap + (size_t)row * B_ + seg * 4);
    }
#pragma unroll
    for (int i = 0; i < 6; i++) {
        int idx = tid + i * 256, tile = idx >> 9, rem = idx & 511, row = rem >> 3, seg = rem & 7;
        cp16(stg + 16384 + tile * 8192 + row * 128 + seg * 16,
             Wp + (size_t)row * (3 * HD) + tile * HD + seg * 4);
    }
}

__device__ __forceinline__ void issue_pred(uint32_t stg, const float* Ap, const float* Wp, int tid)
{
#pragma unroll
    for (int i = 0; i < 4; i++) {
        int idx = tid + i * 256, row = idx >> 4, seg = idx & 15;
        cp16(stg + row * 256 + seg * 16, Ap + (size_t)row * B_ + seg * 4);
    }
    { int row = tid >> 2, seg = tid & 3;
      cp16(stg + 16384 + row * 64 + seg * 16, Wp + (size_t)row * INSZ + seg * 4); }
}

__device__ __forceinline__ const float* gate_A(const float* xb_, const float* hb, int c, int b0)
{ return (c < 8) ? xb_ + (size_t)(c * 64) * B_ + b0 : hb + (size_t)((c - 8) * 64) * B_ + b0; }
__device__ __forceinline__ const float* gate_W(const float* wx, const float* wh, int c, int j0)
{ return (c < 8) ? wx + (size_t)(c * 64) * (3 * HD) + j0 : wh + (size_t)((c - 8) * 64) * (3 * HD) + j0; }

// ---------------- compute ----------------
// Gate microtile: 2j (one u64 pair) x 4b. Per kk: 1 LDS.128 (A) + 3 LDS.64 (W),
// 4 dup-packs, 12 FFMA2. Raw smem bytes/lane = 40 (vs 56 before).
__device__ __forceinline__ void gate_compute(const char* stg, int gx, int gy,
    u64 (&au)[4], u64 (&ar)[4], u64 (&an)[4])
{
    const float* As = (const float*)stg;
    const char* W = stg + 16384;
#pragma unroll 8
    for (int kk = 0; kk < 64; kk++) {
        float4 a4 = *(const float4*)(As + kk * 64 + gy * 4);
        u64 wu = *(const u64*)(W + kk * 128 + gx * 8);
        u64 wr = *(const u64*)(W + 8192 + kk * 128 + gx * 8);
        u64 wn = *(const u64*)(W + 16384 + kk * 128 + gx * 8);
        u64 A0 = pack2(a4.x, a4.x), A1 = pack2(a4.y, a4.y);
        u64 A2 = pack2(a4.z, a4.z), A3 = pack2(a4.w, a4.w);
        ffma2(au[0], A0, wu); ffma2(ar[0], A0, wr); ffma2(an[0], A0, wn);
        ffma2(au[1], A1, wu); ffma2(ar[1], A1, wr); ffma2(an[1], A1, wn);
        ffma2(au[2], A2, wu); ffma2(ar[2], A2, wr); ffma2(an[2], A2, wn);
        ffma2(au[3], A3, wu); ffma2(ar[3], A3, wr); ffma2(an[3], A3, wn);
    }
}

__device__ __forceinline__ void pred_compute(const char* stg, int tx, int ty, u64 (&acc)[2])
{
    const float* As = (const float*)stg;
    const char* W = stg + 16384;
#pragma unroll 8
    for (int kk = 0; kk < 64; kk++) {
        float2 a2 = *(const float2*)(As + kk * 64 + ty * 2);
        u64 wv = *(const u64*)(W + kk * 64 + tx * 8);
        ffma2(acc[0], pack2(a2.x, a2.x), wv);
        ffma2(acc[1], pack2(a2.y, a2.y), wv);
    }
}

// ---------------------------------------------------------------------------
__global__ void __launch_bounds__(NTHR) sgru_kernel(
    const float* __restrict__ xb, const float* __restrict__ h0,
    const float* __restrict__ Wx, const float* __restrict__ bx,
    const float* __restrict__ Wh, const float* __restrict__ bh,
    const float* __restrict__ Wo, const float* __restrict__ bo,
    float* __restrict__ out)
{
    extern __shared__ __align__(16) char smx[];
    const uint32_t smb = smem_u32(smx);
    const int tid = threadIdx.x, bid = blockIdx.x;
    const int tx = tid & 7, ty = tid >> 3;     // pred mapping: 8 x 2o, 32 x 2b
    const int gx = tid & 15, gy = tid >> 4;    // gate mapping: 16 x 2j, 16 x 4b
    unsigned ls = g_sense;

    // ================= init pass: build k-major copies =================
    {
        const long GT = NBLK * NTHR;
        const long g0 = (long)bid * NTHR + tid;
        for (long d = g0; d < (long)T_ * INSZ * B_; d += GT) {
            int b = (int)(d & 255); long rest = d >> 8;
            int k = (int)(rest & 511); int tt = (int)(rest >> 9);
            g_xT[d] = __ldg(xb + ((size_t)b * T_ + tt) * INSZ + k);
        }
        for (long d = g0; d < (long)4 * INSZ * 3 * HD; d += GT) {
            int J = (int)(d % 3072); long rest = d / 3072;
            int k = (int)(rest & 511); int wi = (int)(rest >> 9);
            g_WxT[d] = __ldg(Wx + ((size_t)wi * 3072 + J) * INSZ + k);
        }
        for (long d = g0; d < (long)4 * HD * 3 * HD; d += GT) {
            int J = (int)(d % 3072); long rest = d / 3072;
            int k = (int)(rest & 1023); int wi = (int)(rest >> 10);
            g_WhT[d] = __ldg(Wh + ((size_t)wi * 3072 + J) * HD + k);
        }
        for (long d = g0; d < (long)4 * (HD + INSZ) * INSZ; d += GT) {
            int o = (int)(d & 511); long rest = d >> 9;
            int k = (int)(rest % 1536); int wi = (int)(rest / 1536);
            g_WoT[d] = __ldg(Wo + ((size_t)wi * INSZ + o) * (HD + INSZ) + k);
        }
        for (long d = g0; d < (long)4 * HD * B_; d += GT) {
            int b = (int)(d & 255); long rest = d >> 8;
            int j = (int)(rest & 1023); int s = (int)(rest >> 10);
            g_hT[0][d] = __ldg(h0 + ((size_t)b * 4 + s) * HD + j);
        }
    }
    grid_barrier(ls);

#pragma unroll 1
    for (int t = 0; t < T_; t++) {
        int rd = t & 1, wr = rd ^ 1;
#pragma unroll 1
        for (int s = 0; s < 4; s++) {
            const int wi = (s == 3) ? 2 : s;   // faithful to the source bug
            const float* xbase = (s == 0) ? g_xT + (size_t)t * INSZ * B_
                                          : g_pT[(s - 1) & 1];
            const float* hrdT = g_hT[rd] + (size_t)s * HD * B_;
            float*       hwrT = g_hT[wr] + (size_t)s * HD * B_;
            const float* wxT = g_WxT + (size_t)wi * INSZ * 3 * HD;
            const float* whT = g_WhT + (size_t)wi * HD * 3 * HD;
            const float* woT = g_WoT + (size_t)wi * (HD + INSZ) * INSZ;

            const int j0 = (bid & 31) * 32;
            const int o0 = (bid & 31) * 16;
            const int b0 = (bid >> 5) * 64;

            // ================= GATE =================
            {
                issue_gate(smb, gate_A(xbase, hrdT, 0, b0), gate_W(wxT, whT, 0, j0), tid); CPCOMMIT();
                issue_gate(smb + STG_B, gate_A(xbase, hrdT, 1, b0), gate_W(wxT, whT, 1, j0), tid); CPCOMMIT();

                u64 au[4], ar[4], axn[4], ahn[4];
                const float* bx3 = bx + wi * 3 * HD;
                const float* bh3 = bh + wi * 3 * HD;
                const int jg = j0 + gx * 2;
                {
                    u64 bu = pack2(bx3[jg] + bh3[jg], bx3[jg + 1] + bh3[jg + 1]);
                    u64 br = pack2(bx3[HD + jg] + bh3[HD + jg], bx3[HD + jg + 1] + bh3[HD + jg + 1]);
                    u64 bxn = pack2(bx3[2 * HD + jg], bx3[2 * HD + jg + 1]);
                    u64 bhn = pack2(bh3[2 * HD + jg], bh3[2 * HD + jg + 1]);
#pragma unroll
                    for (int i = 0; i < 4; i++) {
                        au[i] = bu; ar[i] = br; axn[i] = bxn; ahn[i] = bhn;
                    }
                }
#pragma unroll 1
                for (int c = 0; c < NCH; c++) {
                    if (c < NCH - 1) CPWAIT1(); else CPWAIT0();
                    __syncthreads();
                    if (c + 2 < NCH) {
                        issue_gate(smb + ((c + 2) % 3) * STG_B,
                                   gate_A(xbase, hrdT, c + 2, b0),
                                   gate_W(wxT, whT, c + 2, j0), tid);
                        CPCOMMIT();
                    }
                    if (c < 8)
                        gate_compute(smx + (c % 3) * STG_B, gx, gy, au, ar, axn);
                    else
                        gate_compute(smx + (c % 3) * STG_B, gx, gy, au, ar, ahn);
                }
                // epilogue: every thread owns 2j x 4b outputs
#pragma unroll
                for (int i = 0; i < 4; i++) {
                    int b = b0 + gy * 4 + i;
                    float u0, u1, r0, r1, x0, x1, h0v, h1v;
                    unpack2(au[i], u0, u1);
                    unpack2(ar[i], r0, r1);
                    unpack2(axn[i], x0, x1);
                    unpack2(ahn[i], h0v, h1v);
                    {
                        float u = 1.0f / (1.0f + expf(-u0));
                        float r = 1.0f / (1.0f + expf(-r0));
                        float n = tanhf(x0 + r * h0v);
                        float ho = __ldcg(hrdT + (size_t)jg * B_ + b);
                        hwrT[(size_t)jg * B_ + b] = u * ho + (1.0f - u) * n;
                    }
                    {
                        float u = 1.0f / (1.0f + expf(-u1));
                        float r = 1.0f / (1.0f + expf(-r1));
                        float n = tanhf(x1 + r * h1v);
                        float ho = __ldcg(hrdT + (size_t)(jg + 1) * B_ + b);
                        hwrT[(size_t)(jg + 1) * B_ + b] = u * ho + (1.0f - u) * n;
                    }
                }
            }
            // pred prologue (x-chunks + immutable Wo): safe before the barrier
            issue_pred(smb, gate_A(xbase, g_hT[wr] + (size_t)s * HD * B_, 0, b0),
                       woT + 0 * INSZ + o0, tid); CPCOMMIT();
            issue_pred(smb + STG_B, gate_A(xbase, g_hT[wr] + (size_t)s * HD * B_, 1, b0),
                       woT + (size_t)64 * INSZ + o0, tid); CPCOMMIT();
            grid_barrier(ls);

            // ================= PRED =================
            {
                const float* hnT = g_hT[wr] + (size_t)s * HD * B_;
                const float* bop = bo + wi * INSZ;
                u64 acc[2];
                acc[0] = acc[1] = pack2(bop[o0 + tx * 2], bop[o0 + tx * 2 + 1]);
#pragma unroll 1
                for (int c = 0; c < NCH; c++) {
                    if (c < NCH - 1) CPWAIT1(); else CPWAIT0();
                    __syncthreads();
                    if (c + 2 < NCH) {
                        issue_pred(smb + ((c + 2) % 3) * STG_B,
                                   gate_A(xbase, hnT, c + 2, b0),
                                   woT + (size_t)((c + 2) * 64) * INSZ + o0, tid);
                        CPCOMMIT();
                    }
                    pred_compute(smx + (c % 3) * STG_B, tx, ty, acc);
                }
                int o = o0 + tx * 2;
#pragma unroll
                for (int i = 0; i < 2; i++) {
                    int b = b0 + ty * 2 + i;
                    float v0, v1;
                    unpack2(acc[i], v0, v1);
                    if (s == 3) {
                        *(float2*)(out + ((size_t)b * T_ + t) * INSZ + o) = make_float2(v0, v1);
                    } else {
                        float* pT = g_pT[s & 1];
                        pT[(size_t)o * B_ + b] = v0;
                        pT[(size_t)(o + 1) * B_ + b] = v1;
                    }
                }
            }
            grid_barrier(ls);
        }
    }

    // ---- final h copy-out (hT[0] -> out tail, standard layout) ----
    {
        const long GT = NBLK * NTHR;
        for (long d = (long)bid * NTHR + tid; d < (long)B_ * 4 * HD; d += GT) {
            int j = (int)(d & 1023); long rest = d >> 10;
            int s = (int)(rest & 3); int b = (int)(rest >> 2);
            out[(size_t)B_ * T_ * INSZ + d] = __ldcg(&g_hT[0][((size_t)s * HD + j) * B_ + b]);
        }
    }
    // ---- log_softmax over each 512-wide pred row ----
    {
        int w = tid >> 5, ln = tid & 31;
        int gw = bid * 8 + w;
#pragma unroll 1
        for (int r = gw; r < B_ * T_; r += NBLK * 8) {
            float* p = out + (size_t)r * INSZ;
            float v[16], m = -1e30f;
#pragma unroll
            for (int i = 0; i < 16; i++) { v[i] = __ldcg(p + ln + i * 32); m = fmaxf(m, v[i]); }
#pragma unroll
            for (int o = 16; o > 0; o >>= 1) m = fmaxf(m, __shfl_xor_sync(~0u, m, o));
            float sv = 0.0f;
#pragma unroll
            for (int i = 0; i < 16; i++) sv += expf(v[i] - m);
#pragma unroll
            for (int o = 16; o > 0; o >>= 1) sv += __shfl_xor_sync(~0u, sv, o);
            float lv = m + logf(sv);
#pragma unroll
            for (int i = 0; i < 16; i++) p[ln + i * 32] = v[i] - lv;
        }
    }
}

// ---------------------------------------------------------------------------
extern "C" void kernel_launch(void* const* d_in, const int* in_sizes, int n_in,
                              void* d_out, int out_size)
{
    cudaFuncSetAttribute(sgru_kernel, cudaFuncAttributeMaxDynamicSharedMemorySize, SMEMB);
    sgru_kernel<<<NBLK, NTHR, SMEMB>>>(
        (const float*)d_in[0], (const float*)d_in[1], (const float*)d_in[2],
        (const float*)d_in[3], (const float*)d_in[4], (const float*)d_in[5],
        (const float*)d_in[6], (const float*)d_in[7], (float*)d_out);
}

// round 15
// speedup vs baseline: 1.4953x; 1.2243x over previous
#include <cuda_runtime.h>
#include <math.h>
#include <stdint.h>

#define B_   256
#define T_   256
#define INSZ 512
#define HD   1024
#define NBLK 128
#define NTHR 256
#define NCH  24

typedef unsigned long long u64;

// k-major (transposed) operand buffers, built once per launch in init pass
__device__ float g_xT[T_ * INSZ * B_];          // [t][k][b]
__device__ float g_hT[2][4 * HD * B_];          // [pp][s*HD+j][b]
__device__ float g_pT[2][INSZ * B_];            // [pp][o][b]
__device__ float g_WxT[4 * INSZ * 3 * HD];      // [wi][k][J]
__device__ float g_WhT[4 * HD * 3 * HD];
__device__ float g_WoT[4 * (HD + INSZ) * INSZ]; // [wi][k][o]

__device__ unsigned g_count;
__device__ volatile unsigned g_sense;

__device__ __forceinline__ void grid_barrier(unsigned& ls)
{
    __syncthreads();
    if (threadIdx.x == 0) {
        unsigned s = ls ^ 1u;
        __threadfence();
        if (atomicAdd(&g_count, 1u) == NBLK - 1) {
            g_count = 0;
            __threadfence();
            g_sense = s;
        } else {
            while (g_sense != s) { __nanosleep(32); }
        }
        __threadfence();
        ls = s;
    }
    __syncthreads();
}

__device__ __forceinline__ u64 pack2(float lo, float hi)
{ u64 r; asm("mov.b64 %0, {%1, %2};" : "=l"(r) : "f"(lo), "f"(hi)); return r; }
__device__ __forceinline__ void unpack2(u64 v, float& lo, float& hi)
{ asm("mov.b64 {%0, %1}, %2;" : "=f"(lo), "=f"(hi) : "l"(v)); }
__device__ __forceinline__ void ffma2(u64& d, u64 a, u64 b)
{ asm("fma.rn.f32x2 %0, %1, %2, %0;" : "+l"(d) : "l"(a), "l"(b)); }
__device__ __forceinline__ u64 addf2(u64 a, u64 b)
{ u64 r; asm("add.rn.f32x2 %0, %1, %2;" : "=l"(r) : "l"(a), "l"(b)); return r; }

__device__ __forceinline__ uint32_t smem_u32(const void* p)
{ uint32_t a; asm("{ .reg .u64 t; cvta.to.shared.u64 t, %1; cvt.u32.u64 %0, t; }" : "=r"(a) : "l"(p)); return a; }

__device__ __forceinline__ void cp16(uint32_t dst, const float* src)
{ asm volatile("cp.async.cg.shared.global [%0], [%1], 16;" :: "r"(dst), "l"(src)); }

#define CPCOMMIT() asm volatile("cp.async.commit_group;" ::: "memory")
#define CPWAIT1()  asm volatile("cp.async.wait_group 1;" ::: "memory")
#define CPWAIT0()  asm volatile("cp.async.wait_group 0;" ::: "memory")

// stage layout: A tile [64k][64b] floats @0 (16384 B); W tiles @16384
// gate: 3 x [64k][32j] (8192 B each); pred: [64k][16o] (4096 B)
#define STG_B 40960
#define SMEMB (3 * STG_B)

// ---------------- cp.async issue helpers ----------------
__device__ __forceinline__ void issue_gate(uint32_t stg, const float* Ap, const float* Wp, int tid)
{
#pragma unroll
    for (int i = 0; i < 4; i++) {
        int idx = tid + i * 256, row = idx >> 4, seg = idx & 15;
        cp16(stg + row * 256 + seg * 16, Ap + (size_t)row * B_ + seg * 4);
    }
#pragma unroll
    for (int i = 0; i < 6; i++) {
        int idx = tid + i * 256, tile = idx >> 9, rem = idx & 511, row = rem >> 3, seg = rem & 7;
        cp16(stg + 16384 + tile * 8192 + row * 128 + seg * 16,
             Wp + (size_t)row * (3 * HD) + tile * HD + seg * 4);
    }
}

__device__ __forceinline__ void issue_pred(uint32_t stg, const float* Ap, const float* Wp, int tid)
{
#pragma unroll
    for (int i = 0; i < 4; i++) {
        int idx = tid + i * 256, row = idx >> 4, seg = idx & 15;
        cp16(stg + row * 256 + seg * 16, Ap + (size_t)row * B_ + seg * 4);
    }
    { int row = tid >> 2, seg = tid & 3;
      cp16(stg + 16384 + row * 64 + seg * 16, Wp + (size_t)row * INSZ + seg * 4); }
}

__device__ __forceinline__ const float* gate_A(const float* xb_, const float* hb, int c, int b0)
{ return (c < 8) ? xb_ + (size_t)(c * 64) * B_ + b0 : hb + (size_t)((c - 8) * 64) * B_ + b0; }
__device__ __forceinline__ const float* gate_W(const float* wx, const float* wh, int c, int j0)
{ return (c < 8) ? wx + (size_t)(c * 64) * (3 * HD) + j0 : wh + (size_t)((c - 8) * 64) * (3 * HD) + j0; }

// ---------------- compute ----------------
// Gate microtile: 2j x 8b (4 b-pairs), acc packed over b. Per kk:
// 2 LDS.128 (A as 4 u64 b-pairs, no packing) + 3 LDS.64 (W j-pairs) +
// 6 dup-packs + 24 FFMA2. Raw bytes/lane = 56 for 24 ops (2.33 B/op).
__device__ __forceinline__ void gate_compute(const char* stg, int gx, int gy, int kh,
    u64 (&au)[2][4], u64 (&ar)[2][4], u64 (&an)[2][4])
{
    const float* As = (const float*)stg;
    const char* W = stg + 16384;
#pragma unroll 8
    for (int kk = 0; kk < 32; kk++) {
        int ka = kh + kk;
        ulonglong2 aA = *(const ulonglong2*)(As + ka * 64 + gy * 8);
        ulonglong2 aB = *(const ulonglong2*)(As + ka * 64 + gy * 8 + 4);
        float2 wu = *(const float2*)(W + ka * 128 + gx * 8);
        float2 wr = *(const float2*)(W + 8192 + ka * 128 + gx * 8);
        float2 wn = *(const float2*)(W + 16384 + ka * 128 + gx * 8);
        u64 U0 = pack2(wu.x, wu.x), U1 = pack2(wu.y, wu.y);
        u64 R0 = pack2(wr.x, wr.x), R1 = pack2(wr.y, wr.y);
        u64 N0 = pack2(wn.x, wn.x), N1 = pack2(wn.y, wn.y);
        ffma2(au[0][0], U0, aA.x); ffma2(au[0][1], U0, aA.y);
        ffma2(au[0][2], U0, aB.x); ffma2(au[0][3], U0, aB.y);
        ffma2(au[1][0], U1, aA.x); ffma2(au[1][1], U1, aA.y);
        ffma2(au[1][2], U1, aB.x); ffma2(au[1][3], U1, aB.y);
        ffma2(ar[0][0], R0, aA.x); ffma2(ar[0][1], R0, aA.y);
        ffma2(ar[0][2], R0, aB.x); ffma2(ar[0][3], R0, aB.y);
        ffma2(ar[1][0], R1, aA.x); ffma2(ar[1][1], R1, aA.y);
        ffma2(ar[1][2], R1, aB.x); ffma2(ar[1][3], R1, aB.y);
        ffma2(an[0][0], N0, aA.x); ffma2(an[0][1], N0, aA.y);
        ffma2(an[0][2], N0, aB.x); ffma2(an[0][3], N0, aB.y);
        ffma2(an[1][0], N1, aA.x); ffma2(an[1][1], N1, aA.y);
        ffma2(an[1][2], N1, aB.x); ffma2(an[1][3], N1, aB.y);
    }
}

// Pred microtile: 2o x 4b (2 b-pairs). Per kk: 1 LDS.128 (A) + 1 LDS.64 (W) +
// 2 dup-packs + 8 FFMA2. 24 B/lane for 8 ops.
__device__ __forceinline__ void pred_compute(const char* stg, int px, int py, int kh,
    u64 (&acc)[2][2])
{
    const float* As = (const float*)stg;
    const char* W = stg + 16384;
#pragma unroll 8
    for (int kk = 0; kk < 32; kk++) {
        int ka = kh + kk;
        ulonglong2 a2 = *(const ulonglong2*)(As + ka * 64 + py * 4);
        float2 w = *(const float2*)(W + ka * 64 + px * 8);
        u64 W0 = pack2(w.x, w.x), W1 = pack2(w.y, w.y);
        ffma2(acc[0][0], W0, a2.x); ffma2(acc[0][1], W0, a2.y);
        ffma2(acc[1][0], W1, a2.x); ffma2(acc[1][1], W1, a2.y);
    }
}

// ---------------------------------------------------------------------------
__global__ void __launch_bounds__(NTHR) sgru_kernel(
    const float* __restrict__ xb, const float* __restrict__ h0,
    const float* __restrict__ Wx, const float* __restrict__ bx,
    const float* __restrict__ Wh, const float* __restrict__ bh,
    const float* __restrict__ Wo, const float* __restrict__ bo,
    float* __restrict__ out)
{
    extern __shared__ __align__(16) char smx[];
    const uint32_t smb = smem_u32(smx);
    u64* red = (u64*)(smx + 2 * STG_B);   // reduction in stage 2 (free at epilogue)
    const int tid = threadIdx.x, bid = blockIdx.x;
    const int tid2 = tid & 127, half = tid >> 7, kh = half * 32;
    const int gx = tid2 & 15, gy = tid2 >> 4;   // gate: 16 j-pairs, 8 x 8b
    const int px = tid2 & 7,  py = tid2 >> 3;   // pred: 8 o-pairs, 16 x 4b
    unsigned ls = g_sense;

    // ================= init pass: build k-major copies =================
    {
        const long GT = NBLK * NTHR;
        const long g0 = (long)bid * NTHR + tid;
        for (long d = g0; d < (long)T_ * INSZ * B_; d += GT) {
            int b = (int)(d & 255); long rest = d >> 8;
            int k = (int)(rest & 511); int tt = (int)(rest >> 9);
            g_xT[d] = __ldg(xb + ((size_t)b * T_ + tt) * INSZ + k);
        }
        for (long d = g0; d < (long)4 * INSZ * 3 * HD; d += GT) {
            int J = (int)(d % 3072); long rest = d / 3072;
            int k = (int)(rest & 511); int wi = (int)(rest >> 9);
            g_WxT[d] = __ldg(Wx + ((size_t)wi * 3072 + J) * INSZ + k);
        }
        for (long d = g0; d < (long)4 * HD * 3 * HD; d += GT) {
            int J = (int)(d % 3072); long rest = d / 3072;
            int k = (int)(rest & 1023); int wi = (int)(rest >> 10);
            g_WhT[d] = __ldg(Wh + ((size_t)wi * 3072 + J) * HD + k);
        }
        for (long d = g0; d < (long)4 * (HD + INSZ) * INSZ; d += GT) {
            int o = (int)(d & 511); long rest = d >> 9;
            int k = (int)(rest % 1536); int wi = (int)(rest / 1536);
            g_WoT[d] = __ldg(Wo + ((size_t)wi * INSZ + o) * (HD + INSZ) + k);
        }
        for (long d = g0; d < (long)4 * HD * B_; d += GT) {
            int b = (int)(d & 255); long rest = d >> 8;
            int j = (int)(rest & 1023); int s = (int)(rest >> 10);
            g_hT[0][d] = __ldg(h0 + ((size_t)b * 4 + s) * HD + j);
        }
    }
    grid_barrier(ls);

#pragma unroll 1
    for (int t = 0; t < T_; t++) {
        int rd = t & 1, wr = rd ^ 1;
#pragma unroll 1
        for (int s = 0; s < 4; s++) {
            const int wi = (s == 3) ? 2 : s;   // faithful to the source bug
            const float* xbase = (s == 0) ? g_xT + (size_t)t * INSZ * B_
                                          : g_pT[(s - 1) & 1];
            const float* hrdT = g_hT[rd] + (size_t)s * HD * B_;
            float*       hwrT = g_hT[wr] + (size_t)s * HD * B_;
            const float* wxT = g_WxT + (size_t)wi * INSZ * 3 * HD;
            const float* whT = g_WhT + (size_t)wi * HD * 3 * HD;
            const float* woT = g_WoT + (size_t)wi * (HD + INSZ) * INSZ;

            const int j0 = (bid & 31) * 32;
            const int o0 = (bid & 31) * 16;
            const int b0 = (bid >> 5) * 64;

            // ================= GATE =================
            {
                issue_gate(smb, gate_A(xbase, hrdT, 0, b0), gate_W(wxT, whT, 0, j0), tid); CPCOMMIT();
                issue_gate(smb + STG_B, gate_A(xbase, hrdT, 1, b0), gate_W(wxT, whT, 1, j0), tid); CPCOMMIT();

                u64 au[2][4], ar[2][4], axn[2][4], ahn[2][4];
                const float* bx3 = bx + wi * 3 * HD;
                const float* bh3 = bh + wi * 3 * HD;
                const int jg = j0 + gx * 2;
                if (half == 0) {
#pragma unroll
                    for (int j = 0; j < 2; j++) {
                        float bu = bx3[jg + j] + bh3[jg + j];
                        float br = bx3[HD + jg + j] + bh3[HD + jg + j];
                        float bxn = bx3[2 * HD + jg + j];
                        float bhn = bh3[2 * HD + jg + j];
#pragma unroll
                        for (int bp = 0; bp < 4; bp++) {
                            au[j][bp] = pack2(bu, bu); ar[j][bp] = pack2(br, br);
                            axn[j][bp] = pack2(bxn, bxn); ahn[j][bp] = pack2(bhn, bhn);
                        }
                    }
                } else {
#pragma unroll
                    for (int j = 0; j < 2; j++)
#pragma unroll
                        for (int bp = 0; bp < 4; bp++) {
                            au[j][bp] = 0; ar[j][bp] = 0; axn[j][bp] = 0; ahn[j][bp] = 0;
                        }
                }
#pragma unroll 1
                for (int c = 0; c < NCH; c++) {
                    if (c < NCH - 1) CPWAIT1(); else CPWAIT0();
                    __syncthreads();
                    if (c + 2 < NCH) {
                        issue_gate(smb + ((c + 2) % 3) * STG_B,
                                   gate_A(xbase, hrdT, c + 2, b0),
                                   gate_W(wxT, whT, c + 2, j0), tid);
                        CPCOMMIT();
                    }
                    if (c < 8)
                        gate_compute(smx + (c % 3) * STG_B, gx, gy, kh, au, ar, axn);
                    else
                        gate_compute(smx + (c % 3) * STG_B, gx, gy, kh, au, ar, ahn);
                }
                // cross-half reduction (stage 2 is free now; resync first)
                __syncthreads();
                if (half) {
                    u64* rp = red + (size_t)tid2 * 33;
#pragma unroll
                    for (int j = 0; j < 2; j++)
#pragma unroll
                        for (int bp = 0; bp < 4; bp++) {
                            rp[j * 4 + bp] = au[j][bp];
                            rp[8 + j * 4 + bp] = ar[j][bp];
                            rp[16 + j * 4 + bp] = axn[j][bp];
                            rp[24 + j * 4 + bp] = ahn[j][bp];
                        }
                }
                __syncthreads();
                if (!half) {
                    u64* rp = red + (size_t)tid2 * 33;
#pragma unroll
                    for (int j = 0; j < 2; j++)
#pragma unroll
                        for (int bp = 0; bp < 4; bp++) {
                            au[j][bp] = addf2(au[j][bp], rp[j * 4 + bp]);
                            ar[j][bp] = addf2(ar[j][bp], rp[8 + j * 4 + bp]);
                            axn[j][bp] = addf2(axn[j][bp], rp[16 + j * 4 + bp]);
                            ahn[j][bp] = addf2(ahn[j][bp], rp[24 + j * 4 + bp]);
                        }
                    // epilogue: 2j x 8b per thread (float2 over b-pairs)
#pragma unroll
                    for (int j = 0; j < 2; j++) {
                        size_t rowo = (size_t)(jg + j) * B_;
#pragma unroll
                        for (int bp = 0; bp < 4; bp++) {
                            int b = b0 + gy * 8 + bp * 2;
                            float u0, u1, r0, r1, x0, x1, hn0, hn1;
                            unpack2(au[j][bp], u0, u1);
                            unpack2(ar[j][bp], r0, r1);
                            unpack2(axn[j][bp], x0, x1);
                            unpack2(ahn[j][bp], hn0, hn1);
                            float2 ho = __ldcg((const float2*)(hrdT + rowo + b));
                            float ua = 1.0f / (1.0f + expf(-u0));
                            float ub = 1.0f / (1.0f + expf(-u1));
                            float ra = 1.0f / (1.0f + expf(-r0));
                            float rb = 1.0f / (1.0f + expf(-r1));
                            float na = tanhf(x0 + ra * hn0);
                            float nb = tanhf(x1 + rb * hn1);
                            float2 hv = make_float2(ua * ho.x + (1.0f - ua) * na,
                                                    ub * ho.y + (1.0f - ub) * nb);
                            *(float2*)(hwrT + rowo + b) = hv;
                        }
                    }
                }
            }
            // pred prologue (x-chunks + immutable Wo): safe before the barrier
            issue_pred(smb, gate_A(xbase, g_hT[wr] + (size_t)s * HD * B_, 0, b0),
                       woT + 0 * INSZ + o0, tid); CPCOMMIT();
            issue_pred(smb + STG_B, gate_A(xbase, g_hT[wr] + (size_t)s * HD * B_, 1, b0),
                       woT + (size_t)64 * INSZ + o0, tid); CPCOMMIT();
            grid_barrier(ls);

            // ================= PRED =================
            {
                const float* hnT = g_hT[wr] + (size_t)s * HD * B_;
                const float* bop = bo + wi * INSZ;
                u64 acc[2][2];
                if (half == 0) {
                    float b0v = bop[o0 + px * 2], b1v = bop[o0 + px * 2 + 1];
                    acc[0][0] = acc[0][1] = pack2(b0v, b0v);
                    acc[1][0] = acc[1][1] = pack2(b1v, b1v);
                } else {
                    acc[0][0] = acc[0][1] = 0;
                    acc[1][0] = acc[1][1] = 0;
                }
#pragma unroll 1
                for (int c = 0; c < NCH; c++) {
                    if (c < NCH - 1) CPWAIT1(); else CPWAIT0();
                    __syncthreads();
                    if (c + 2 < NCH) {
                        issue_pred(smb + ((c + 2) % 3) * STG_B,
                                   gate_A(xbase, hnT, c + 2, b0),
                                   woT + (size_t)((c + 2) * 64) * INSZ + o0, tid);
                        CPCOMMIT();
                    }
                    pred_compute(smx + (c % 3) * STG_B, px, py, kh, acc);
                }
                // cross-half reduction (stage 2 free)
                __syncthreads();
                if (half) {
                    u64* rp = red + (size_t)tid2 * 33;
                    rp[0] = acc[0][0]; rp[1] = acc[0][1];
                    rp[2] = acc[1][0]; rp[3] = acc[1][1];
                }
                __syncthreads();
                if (!half) {
                    u64* rp = red + (size_t)tid2 * 33;
                    acc[0][0] = addf2(acc[0][0], rp[0]);
                    acc[0][1] = addf2(acc[0][1], rp[1]);
                    acc[1][0] = addf2(acc[1][0], rp[2]);
                    acc[1][1] = addf2(acc[1][1], rp[3]);

                    // epilogue: 2o x 4b per thread
#pragma unroll
                    for (int i = 0; i < 2; i++) {
                        int o = o0 + px * 2 + i;
#pragma unroll
                        for (int bp = 0; bp < 2; bp++) {
                            int b = b0 + py * 4 + bp * 2;
                            float v0, v1;
                            unpack2(acc[i][bp], v0, v1);
                            if (s == 3) {
                                out[((size_t)b * T_ + t) * INSZ + o] = v0;
                                out[((size_t)(b + 1) * T_ + t) * INSZ + o] = v1;
                            } else {
                                *(float2*)(g_pT[s & 1] + (size_t)o * B_ + b) = make_float2(v0, v1);
                            }
                        }
                    }
                }
            }
            grid_barrier(ls);
        }
    }

    // ---- final h copy-out (hT[0] -> out tail, standard layout) ----
    {
        const long GT = NBLK * NTHR;
        for (long d = (long)bid * NTHR + tid; d < (long)B_ * 4 * HD; d += GT) {
            int j = (int)(d & 1023); long rest = d >> 10;
            int s = (int)(rest & 3); int b = (int)(rest >> 2);
            out[(size_t)B_ * T_ * INSZ + d] = __ldcg(&g_hT[0][((size_t)s * HD + j) * B_ + b]);
        }
    }
    // ---- log_softmax over each 512-wide pred row ----
    {
        int w = tid >> 5, ln = tid & 31;
        int gw = bid * 8 + w;
#pragma unroll 1
        for (int r = gw; r < B_ * T_; r += NBLK * 8) {
            float* p = out + (size_t)r * INSZ;
            float v[16], m = -1e30f;
#pragma unroll
            for (int i = 0; i < 16; i++) { v[i] = __ldcg(p + ln + i * 32); m = fmaxf(m, v[i]); }
#pragma unroll
            for (int o = 16; o > 0; o >>= 1) m = fmaxf(m, __shfl_xor_sync(~0u, m, o));
            float sv = 0.0f;
#pragma unroll
            for (int i = 0; i < 16; i++) sv += expf(v[i] - m);
#pragma unroll
            for (int o = 16; o > 0; o >>= 1) sv += __shfl_xor_sync(~0u, sv, o);
            float lv = m + logf(sv);
#pragma unroll
            for (int i = 0; i < 16; i++) p[ln + i * 32] = v[i] - lv;
        }
    }
}

// ---------------------------------------------------------------------------
extern "C" void kernel_launch(void* const* d_in, const int* in_sizes, int n_in,
                              void* d_out, int out_size)
{
    cudaFuncSetAttribute(sgru_kernel, cudaFuncAttributeMaxDynamicSharedMemorySize, SMEMB);
    sgru_kernel<<<NBLK, NTHR, SMEMB>>>(
        (const float*)d_in[0], (const float*)d_in[1], (const float*)d_in[2],
        (const float*)d_in[3], (const float*)d_in[4], (const float*)d_in[5],
        (const float*)d_in[6], (const float*)d_in[7], (float*)d_out);
}

// round 16
// speedup vs baseline: 1.6089x; 1.0760x over previous
#include <cuda_runtime.h>
#include <math.h>
#include <stdint.h>

#define B_   256
#define T_   256
#define INSZ 512
#define HD   1024
#define NBLK 128
#define NTHR 256
#define NCH  24

typedef unsigned long long u64;

// k-major (transposed) operand buffers, built once per launch in init pass
__device__ float g_xT[T_ * INSZ * B_];          // [t][k][b]
__device__ float g_hT[2][4 * HD * B_];          // [pp][s*HD+j][b]
__device__ float g_pT[2][INSZ * B_];            // [pp][o][b]
__device__ float g_WxT[4 * INSZ * 3 * HD];      // [wi][k][J]
__device__ float g_WhT[4 * HD * 3 * HD];
__device__ float g_WoT[4 * (HD + INSZ) * INSZ]; // [wi][k][o]

__device__ unsigned g_count;
__device__ volatile unsigned g_sense;

__device__ __forceinline__ void grid_barrier(unsigned& ls)
{
    __syncthreads();
    if (threadIdx.x == 0) {
        unsigned s = ls ^ 1u;
        __threadfence();
        if (atomicAdd(&g_count, 1u) == NBLK - 1) {
            g_count = 0;
            __threadfence();
            g_sense = s;
        } else {
            while (g_sense != s) { __nanosleep(32); }
        }
        __threadfence();
        ls = s;
    }
    __syncthreads();
}

__device__ __forceinline__ u64 pack2(float lo, float hi)
{ u64 r; asm("mov.b64 %0, {%1, %2};" : "=l"(r) : "f"(lo), "f"(hi)); return r; }
__device__ __forceinline__ void unpack2(u64 v, float& lo, float& hi)
{ asm("mov.b64 {%0, %1}, %2;" : "=f"(lo), "=f"(hi) : "l"(v)); }
__device__ __forceinline__ void ffma2(u64& d, u64 a, u64 b)
{ asm("fma.rn.f32x2 %0, %1, %2, %0;" : "+l"(d) : "l"(a), "l"(b)); }
__device__ __forceinline__ u64 addf2(u64 a, u64 b)
{ u64 r; asm("add.rn.f32x2 %0, %1, %2;" : "=l"(r) : "l"(a), "l"(b)); return r; }

__device__ __forceinline__ uint32_t smem_u32(const void* p)
{ uint32_t a; asm("{ .reg .u64 t; cvta.to.shared.u64 t, %1; cvt.u32.u64 %0, t; }" : "=r"(a) : "l"(p)); return a; }

__device__ __forceinline__ void cp16(uint32_t dst, const float* src)
{ asm volatile("cp.async.cg.shared.global [%0], [%1], 16;" :: "r"(dst), "l"(src)); }

#define CPCOMMIT() asm volatile("cp.async.commit_group;" ::: "memory")
#define CPWAIT1()  asm volatile("cp.async.wait_group 1;" ::: "memory")
#define CPWAIT0()  asm volatile("cp.async.wait_group 0;" ::: "memory")

// stage layout: A tile [64k][64b] floats @0 (16384 B); W tiles @16384
// gate: 3 x [64k][32j] (8192 B each); pred: [64k][16o] (4096 B)
#define STG_B 40960
#define SMEMB (3 * STG_B)

// ---------------- cp.async issue helpers ----------------
__device__ __forceinline__ void issue_gate(uint32_t stg, const float* Ap, const float* Wp, int tid)
{
#pragma unroll
    for (int i = 0; i < 4; i++) {
        int idx = tid + i * 256, row = idx >> 4, seg = idx & 15;
        cp16(stg + row * 256 + seg * 16, Ap + (size_t)row * B_ + seg * 4);
    }
#pragma unroll
    for (int i = 0; i < 6; i++) {
        int idx = tid + i * 256, tile = idx >> 9, rem = idx & 511, row = rem >> 3, seg = rem & 7;
        cp16(stg + 16384 + tile * 8192 + row * 128 + seg * 16,
             Wp + (size_t)row * (3 * HD) + tile * HD + seg * 4);
    }
}

__device__ __forceinline__ void issue_pred(uint32_t stg, const float* Ap, const float* Wp, int tid)
{
#pragma unroll
    for (int i = 0; i < 4; i++) {
        int idx = tid + i * 256, row = idx >> 4, seg = idx & 15;
        cp16(stg + row * 256 + seg * 16, Ap + (size_t)row * B_ + seg * 4);
    }
    { int row = tid >> 2, seg = tid & 3;
      cp16(stg + 16384 + row * 64 + seg * 16, Wp + (size_t)row * INSZ + seg * 4); }
}

__device__ __forceinline__ const float* gate_A(const float* xb_, const float* hb, int c, int b0)
{ return (c < 8) ? xb_ + (size_t)(c * 64) * B_ + b0 : hb + (size_t)((c - 8) * 64) * B_ + b0; }
__device__ __forceinline__ const float* gate_W(const float* wx, const float* wh, int c, int j0)
{ return (c < 8) ? wx + (size_t)(c * 64) * (3 * HD) + j0 : wh + (size_t)((c - 8) * 64) * (3 * HD) + j0; }

// ---------------- compute ----------------
// Gate microtile: 2j x 8b (4 b-pairs), acc packed over b. 2-way k-split.
__device__ __forceinline__ void gate_compute(const char* stg, int gx, int gy, int kh,
    u64 (&au)[2][4], u64 (&ar)[2][4], u64 (&an)[2][4])
{
    const float* As = (const float*)stg;
    const char* W = stg + 16384;
#pragma unroll 8
    for (int kk = 0; kk < 32; kk++) {
        int ka = kh + kk;
        ulonglong2 aA = *(const ulonglong2*)(As + ka * 64 + gy * 8);
        ulonglong2 aB = *(const ulonglong2*)(As + ka * 64 + gy * 8 + 4);
        float2 wu = *(const float2*)(W + ka * 128 + gx * 8);
        float2 wr = *(const float2*)(W + 8192 + ka * 128 + gx * 8);
        float2 wn = *(const float2*)(W + 16384 + ka * 128 + gx * 8);
        u64 U0 = pack2(wu.x, wu.x), U1 = pack2(wu.y, wu.y);
        u64 R0 = pack2(wr.x, wr.x), R1 = pack2(wr.y, wr.y);
        u64 N0 = pack2(wn.x, wn.x), N1 = pack2(wn.y, wn.y);
        ffma2(au[0][0], U0, aA.x); ffma2(au[0][1], U0, aA.y);
        ffma2(au[0][2], U0, aB.x); ffma2(au[0][3], U0, aB.y);
        ffma2(au[1][0], U1, aA.x); ffma2(au[1][1], U1, aA.y);
        ffma2(au[1][2], U1, aB.x); ffma2(au[1][3], U1, aB.y);
        ffma2(ar[0][0], R0, aA.x); ffma2(ar[0][1], R0, aA.y);
        ffma2(ar[0][2], R0, aB.x); ffma2(ar[0][3], R0, aB.y);
        ffma2(ar[1][0], R1, aA.x); ffma2(ar[1][1], R1, aA.y);
        ffma2(ar[1][2], R1, aB.x); ffma2(ar[1][3], R1, aB.y);
        ffma2(an[0][0], N0, aA.x); ffma2(an[0][1], N0, aA.y);
        ffma2(an[0][2], N0, aB.x); ffma2(an[0][3], N0, aB.y);
        ffma2(an[1][0], N1, aA.x); ffma2(an[1][1], N1, aA.y);
        ffma2(an[1][2], N1, aB.x); ffma2(an[1][3], N1, aB.y);
    }
}

// Pred microtile: 4o x 8b (4 b-pairs), 32 output threads, 8-way k-split.
// Per kk: 2 LDS.128 (A) + 1 LDS.128 (W) + 4 dup-packs + 16 FFMA2 (3.0 B/op).
__device__ __forceinline__ void pred_compute(const char* stg, int ppx, int ppy, int pkh,
    u64 (&acc)[4][4])
{
    const float* As = (const float*)stg;
    const char* W = stg + 16384;
#pragma unroll
    for (int kk = 0; kk < 8; kk++) {
        int ka = pkh + kk;
        ulonglong2 aA = *(const ulonglong2*)(As + ka * 64 + ppy * 8);
        ulonglong2 aB = *(const ulonglong2*)(As + ka * 64 + ppy * 8 + 4);
        float4 w = *(const float4*)(W + ka * 64 + ppx * 16);
        u64 W0 = pack2(w.x, w.x), W1 = pack2(w.y, w.y);
        u64 W2 = pack2(w.z, w.z), W3 = pack2(w.w, w.w);
        ffma2(acc[0][0], W0, aA.x); ffma2(acc[0][1], W0, aA.y);
        ffma2(acc[0][2], W0, aB.x); ffma2(acc[0][3], W0, aB.y);
        ffma2(acc[1][0], W1, aA.x); ffma2(acc[1][1], W1, aA.y);
        ffma2(acc[1][2], W1, aB.x); ffma2(acc[1][3], W1, aB.y);
        ffma2(acc[2][0], W2, aA.x); ffma2(acc[2][1], W2, aA.y);
        ffma2(acc[2][2], W2, aB.x); ffma2(acc[2][3], W2, aB.y);
        ffma2(acc[3][0], W3, aA.x); ffma2(acc[3][1], W3, aA.y);
        ffma2(acc[3][2], W3, aB.x); ffma2(acc[3][3], W3, aB.y);
    }
}

// ---------------------------------------------------------------------------
__global__ void __launch_bounds__(NTHR) sgru_kernel(
    const float* __restrict__ xb, const float* __restrict__ h0,
    const float* __restrict__ Wx, const float* __restrict__ bx,
    const float* __restrict__ Wh, const float* __restrict__ bh,
    const float* __restrict__ Wo, const float* __restrict__ bo,
    float* __restrict__ out)
{
    extern __shared__ __align__(16) char smx[];
    const uint32_t smb = smem_u32(smx);
    u64* red = (u64*)(smx + 2 * STG_B);   // reduction in stage 2 (free at epilogue)
    const int tid = threadIdx.x, bid = blockIdx.x;
    const int tid2 = tid & 127, half = tid >> 7, kh = half * 32;
    const int gx = tid2 & 15, gy = tid2 >> 4;   // gate: 16 j-pairs, 8 x 8b
    const int t32 = tid & 31, oct = tid >> 5, pkh = oct * 8;   // pred: 8-way split
    const int ppx = t32 & 3, ppy = t32 >> 2;    // pred: 4 o-quads, 8 x 8b
    unsigned ls = g_sense;

    // ================= init pass: build k-major copies =================
    {
        const long GT = NBLK * NTHR;
        const long g0 = (long)bid * NTHR + tid;
        for (long d = g0; d < (long)T_ * INSZ * B_; d += GT) {
            int b = (int)(d & 255); long rest = d >> 8;
            int k = (int)(rest & 511); int tt = (int)(rest >> 9);
            g_xT[d] = __ldg(xb + ((size_t)b * T_ + tt) * INSZ + k);
        }
        for (long d = g0; d < (long)4 * INSZ * 3 * HD; d += GT) {
            int J = (int)(d % 3072); long rest = d / 3072;
            int k = (int)(rest & 511); int wi = (int)(rest >> 9);
            g_WxT[d] = __ldg(Wx + ((size_t)wi * 3072 + J) * INSZ + k);
        }
        for (long d = g0; d < (long)4 * HD * 3 * HD; d += GT) {
            int J = (int)(d % 3072); long rest = d / 3072;
            int k = (int)(rest & 1023); int wi = (int)(rest >> 10);
            g_WhT[d] = __ldg(Wh + ((size_t)wi * 3072 + J) * HD + k);
        }
        for (long d = g0; d < (long)4 * (HD + INSZ) * INSZ; d += GT) {
            int o = (int)(d & 511); long rest = d >> 9;
            int k = (int)(rest % 1536); int wi = (int)(rest / 1536);
            g_WoT[d] = __ldg(Wo + ((size_t)wi * INSZ + o) * (HD + INSZ) + k);
        }
        for (long d = g0; d < (long)4 * HD * B_; d += GT) {
            int b = (int)(d & 255); long rest = d >> 8;
            int j = (int)(rest & 1023); int s = (int)(rest >> 10);
            g_hT[0][d] = __ldg(h0 + ((size_t)b * 4 + s) * HD + j);
        }
    }
    grid_barrier(ls);

#pragma unroll 1
    for (int t = 0; t < T_; t++) {
        int rd = t & 1, wr = rd ^ 1;
#pragma unroll 1
        for (int s = 0; s < 4; s++) {
            const int wi = (s == 3) ? 2 : s;   // faithful to the source bug
            const float* xbase = (s == 0) ? g_xT + (size_t)t * INSZ * B_
                                          : g_pT[(s - 1) & 1];
            const float* hrdT = g_hT[rd] + (size_t)s * HD * B_;
            float*       hwrT = g_hT[wr] + (size_t)s * HD * B_;
            const float* wxT = g_WxT + (size_t)wi * INSZ * 3 * HD;
            const float* whT = g_WhT + (size_t)wi * HD * 3 * HD;
            const float* woT = g_WoT + (size_t)wi * (HD + INSZ) * INSZ;

            const int j0 = (bid & 31) * 32;
            const int o0 = (bid & 31) * 16;
            const int b0 = (bid >> 5) * 64;

            // ================= GATE =================
            {
                issue_gate(smb, gate_A(xbase, hrdT, 0, b0), gate_W(wxT, whT, 0, j0), tid); CPCOMMIT();
                issue_gate(smb + STG_B, gate_A(xbase, hrdT, 1, b0), gate_W(wxT, whT, 1, j0), tid); CPCOMMIT();

                u64 au[2][4], ar[2][4], axn[2][4], ahn[2][4];
                const float* bx3 = bx + wi * 3 * HD;
                const float* bh3 = bh + wi * 3 * HD;
                const int jg = j0 + gx * 2;
                if (half == 0) {
#pragma unroll
                    for (int j = 0; j < 2; j++) {
                        float bu = bx3[jg + j] + bh3[jg + j];
                        float br = bx3[HD + jg + j] + bh3[HD + jg + j];
                        float bxn = bx3[2 * HD + jg + j];
                        float bhn = bh3[2 * HD + jg + j];
#pragma unroll
                        for (int bp = 0; bp < 4; bp++) {
                            au[j][bp] = pack2(bu, bu); ar[j][bp] = pack2(br, br);
                            axn[j][bp] = pack2(bxn, bxn); ahn[j][bp] = pack2(bhn, bhn);
                        }
                    }
                } else {
#pragma unroll
                    for (int j = 0; j < 2; j++)
#pragma unroll
                        for (int bp = 0; bp < 4; bp++) {
                            au[j][bp] = 0; ar[j][bp] = 0; axn[j][bp] = 0; ahn[j][bp] = 0;
                        }
                }
#pragma unroll 1
                for (int c = 0; c < NCH; c++) {
                    if (c < NCH - 1) CPWAIT1(); else CPWAIT0();
                    __syncthreads();
                    if (c + 2 < NCH) {
                        issue_gate(smb + ((c + 2) % 3) * STG_B,
                                   gate_A(xbase, hrdT, c + 2, b0),
                                   gate_W(wxT, whT, c + 2, j0), tid);
                        CPCOMMIT();
                    }
                    if (c < 8)
                        gate_compute(smx + (c % 3) * STG_B, gx, gy, kh, au, ar, axn);
                    else
                        gate_compute(smx + (c % 3) * STG_B, gx, gy, kh, au, ar, ahn);
                }
                // cross-half reduction (stage 2 is free now; resync first)
                __syncthreads();
                if (half) {
                    u64* rp = red + (size_t)tid2 * 33;
#pragma unroll
                    for (int j = 0; j < 2; j++)
#pragma unroll
                        for (int bp = 0; bp < 4; bp++) {
                            rp[j * 4 + bp] = au[j][bp];
                            rp[8 + j * 4 + bp] = ar[j][bp];
                            rp[16 + j * 4 + bp] = axn[j][bp];
                            rp[24 + j * 4 + bp] = ahn[j][bp];
                        }
                }
                __syncthreads();
                if (!half) {
                    u64* rp = red + (size_t)tid2 * 33;
#pragma unroll
                    for (int j = 0; j < 2; j++)
#pragma unroll
                        for (int bp = 0; bp < 4; bp++) {
                            au[j][bp] = addf2(au[j][bp], rp[j * 4 + bp]);
                            ar[j][bp] = addf2(ar[j][bp], rp[8 + j * 4 + bp]);
                            axn[j][bp] = addf2(axn[j][bp], rp[16 + j * 4 + bp]);
                            ahn[j][bp] = addf2(ahn[j][bp], rp[24 + j * 4 + bp]);
                        }
                    // epilogue: 2j x 8b per thread (float2 over b-pairs)
#pragma unroll
                    for (int j = 0; j < 2; j++) {
                        size_t rowo = (size_t)(jg + j) * B_;
#pragma unroll
                        for (int bp = 0; bp < 4; bp++) {
                            int b = b0 + gy * 8 + bp * 2;
                            float u0, u1, r0, r1, x0, x1, hn0, hn1;
                            unpack2(au[j][bp], u0, u1);
                            unpack2(ar[j][bp], r0, r1);
                            unpack2(axn[j][bp], x0, x1);
                            unpack2(ahn[j][bp], hn0, hn1);
                            float2 ho = __ldcg((const float2*)(hrdT + rowo + b));
                            float ua = 1.0f / (1.0f + expf(-u0));
                            float ub = 1.0f / (1.0f + expf(-u1));
                            float ra = 1.0f / (1.0f + expf(-r0));
                            float rb = 1.0f / (1.0f + expf(-r1));
                            float na = tanhf(x0 + ra * hn0);
                            float nb = tanhf(x1 + rb * hn1);
                            float2 hv = make_float2(ua * ho.x + (1.0f - ua) * na,
                                                    ub * ho.y + (1.0f - ub) * nb);
                            *(float2*)(hwrT + rowo + b) = hv;
                        }
                    }
                }
            }
            // pred prologue (x-chunks + immutable Wo): safe before the barrier
            issue_pred(smb, gate_A(xbase, g_hT[wr] + (size_t)s * HD * B_, 0, b0),
                       woT + 0 * INSZ + o0, tid); CPCOMMIT();
            issue_pred(smb + STG_B, gate_A(xbase, g_hT[wr] + (size_t)s * HD * B_, 1, b0),
                       woT + (size_t)64 * INSZ + o0, tid); CPCOMMIT();
            grid_barrier(ls);

            // ================= PRED =================
            {
                const float* hnT = g_hT[wr] + (size_t)s * HD * B_;
                const float* bop = bo + wi * INSZ;
                u64 acc[4][4];
                if (oct == 0) {
#pragma unroll
                    for (int j = 0; j < 4; j++) {
                        float bv = bop[o0 + ppx * 4 + j];
#pragma unroll
                        for (int bp = 0; bp < 4; bp++) acc[j][bp] = pack2(bv, bv);
                    }
                } else {
#pragma unroll
                    for (int j = 0; j < 4; j++)
#pragma unroll
                        for (int bp = 0; bp < 4; bp++) acc[j][bp] = 0;
                }
#pragma unroll 1
                for (int c = 0; c < NCH; c++) {
                    if (c < NCH - 1) CPWAIT1(); else CPWAIT0();
                    __syncthreads();
                    if (c + 2 < NCH) {
                        issue_pred(smb + ((c + 2) % 3) * STG_B,
                                   gate_A(xbase, hnT, c + 2, b0),
                                   woT + (size_t)((c + 2) * 64) * INSZ + o0, tid);
                        CPCOMMIT();
                    }
                    pred_compute(smx + (c % 3) * STG_B, ppx, ppy, pkh, acc);
                }
                // cross-octave reduction (stage 2 free)
                __syncthreads();
                if (oct) {
                    u64* rp = red + ((size_t)(oct - 1) * 32 + t32) * 17;
#pragma unroll
                    for (int j = 0; j < 4; j++)
#pragma unroll
                        for (int bp = 0; bp < 4; bp++) rp[j * 4 + bp] = acc[j][bp];
                }
                __syncthreads();
                if (oct == 0) {
#pragma unroll
                    for (int q = 0; q < 7; q++) {
                        u64* rp = red + ((size_t)q * 32 + t32) * 17;
#pragma unroll
                        for (int j = 0; j < 4; j++)
#pragma unroll
                            for (int bp = 0; bp < 4; bp++)
                                acc[j][bp] = addf2(acc[j][bp], rp[j * 4 + bp]);
                    }
                    // epilogue: 4o x 8b per thread
#pragma unroll
                    for (int j = 0; j < 4; j++) {
                        int o = o0 + ppx * 4 + j;
#pragma unroll
                        for (int bp = 0; bp < 4; bp++) {
                            int b = b0 + ppy * 8 + bp * 2;
                            float v0, v1;
                            unpack2(acc[j][bp], v0, v1);
                            if (s == 3) {
                                out[((size_t)b * T_ + t) * INSZ + o] = v0;
                                out[((size_t)(b + 1) * T_ + t) * INSZ + o] = v1;
                            } else {
                                *(float2*)(g_pT[s & 1] + (size_t)o * B_ + b) = make_float2(v0, v1);
                            }
                        }
                    }
                }
            }
            grid_barrier(ls);
        }
    }

    // ---- final h copy-out (hT[0] -> out tail, standard layout) ----
    {
        const long GT = NBLK * NTHR;
        for (long d = (long)bid * NTHR + tid; d < (long)B_ * 4 * HD; d += GT) {
            int j = (int)(d & 1023); long rest = d >> 10;
            int s = (int)(rest & 3); int b = (int)(rest >> 2);
            out[(size_t)B_ * T_ * INSZ + d] = __ldcg(&g_hT[0][((size_t)s * HD + j) * B_ + b]);
        }
    }
    // ---- log_softmax over each 512-wide pred row ----
    {
        int w = tid >> 5, ln = tid & 31;
        int gw = bid * 8 + w;
#pragma unroll 1
        for (int r = gw; r < B_ * T_; r += NBLK * 8) {
            float* p = out + (size_t)r * INSZ;
            float v[16], m = -1e30f;
#pragma unroll
            for (int i = 0; i < 16; i++) { v[i] = __ldcg(p + ln + i * 32); m = fmaxf(m, v[i]); }
#pragma unroll
            for (int o = 16; o > 0; o >>= 1) m = fmaxf(m, __shfl_xor_sync(~0u, m, o));
            float sv = 0.0f;
#pragma unroll
            for (int i = 0; i < 16; i++) sv += expf(v[i] - m);
#pragma unroll
            for (int o = 16; o > 0; o >>= 1) sv += __shfl_xor_sync(~0u, sv, o);
            float lv = m + logf(sv);
#pragma unroll
            for (int i = 0; i < 16; i++) p[ln + i * 32] = v[i] - lv;
        }
    }
}

// ---------------------------------------------------------------------------
extern "C" void kernel_launch(void* const* d_in, const int* in_sizes, int n_in,
                              void* d_out, int out_size)
{
    cudaFuncSetAttribute(sgru_kernel, cudaFuncAttributeMaxDynamicSharedMemorySize, SMEMB);
    sgru_kernel<<<NBLK, NTHR, SMEMB>>>(
        (const float*)d_in[0], (const float*)d_in[1], (const float*)d_in[2],
        (const float*)d_in[3], (const float*)d_in[4], (const float*)d_in[5],
        (const float*)d_in[6], (const float*)d_in[7], (float*)d_out);
}